// round 15
// baseline (speedup 1.0000x reference)
#include <cuda_runtime.h>

#define NPTS 32768
#define KNB  64
#define CDIM 256
#define PAIR 32
#define HID  64
#define BINS 16
#define CLIPV 32
#define NDR  (2 * CLIPV + 1)
#define LN_EPS 1e-5f
#define PMUX 2            // pairs per thread per outer iter
#define OUTER 4           // outer iterations per block
#define TPB  128          // 1024 pairs/block, 16 n's/block
#define NPB  16
#define BPAIRS (TPB * PMUX * OUTER)
#define NPAIRS (NPTS * KNB)
#define LOG2E 1.4426950408889634f

typedef unsigned long long u64;

// Scratch (allocation-free rule -> __device__ globals)
static __device__ __align__(256) float g_left[NPTS * PAIR];     // 4 MB
static __device__ __align__(256) float g_right[NPTS * PAIR];    // 4 MB
static __device__ int2  g_meta[NPTS];
static __device__ __align__(256) u64 LPg[NPTS * (HID / 2)];     // 8 MB: left @ W1'
static __device__ __align__(256) u64 RPg[NPTS * (HID / 2)];     // 8 MB: right @ W1'
static __device__ __align__(16)  u64 PPg[NDR * (HID / 2)];      // Wpos @ W1'
static __device__ u64 Sg[HID / 2];                              // col sums of W1'
static __device__ u64 Bg[HID / 2];                              // lnb@W1 + b1

// ---------------- packed f32x2 helpers (FFMA2: PTX-only on sm_103a) --------
__device__ __forceinline__ u64 pk2(float lo, float hi) {
    u64 r; asm("mov.b64 %0,{%1,%2};" : "=l"(r) : "f"(lo), "f"(hi)); return r;
}
__device__ __forceinline__ float2 upk2(u64 v) {
    float2 f; asm("mov.b64 {%0,%1},%2;" : "=f"(f.x), "=f"(f.y) : "l"(v)); return f;
}
__device__ __forceinline__ u64 f2fma(u64 a, u64 b, u64 c) {
    u64 r; asm("fma.rn.f32x2 %0,%1,%2,%3;" : "=l"(r) : "l"(a), "l"(b), "l"(c)); return r;
}
__device__ __forceinline__ u64 f2add(u64 a, u64 b) {
    u64 r; asm("add.rn.f32x2 %0,%1,%2;" : "=l"(r) : "l"(a), "l"(b)); return r;
}
__device__ __forceinline__ float tanh_approx(float x) {
    float r; asm("tanh.approx.f32 %0,%1;" : "=f"(r) : "f"(x)); return r;
}
__device__ __forceinline__ float ex2f(float x) {
    float r; asm("ex2.approx.f32 %0,%1;" : "=f"(r) : "f"(x)); return r;
}

// ---------------------------------------------------------------------------
// Kernel 0: pack per-residue metadata
// ---------------------------------------------------------------------------
__global__ __launch_bounds__(256) void meta_kernel(
    const int* __restrict__ resi, const int* __restrict__ chain,
    const int* __restrict__ batch)
{
    int i = blockIdx.x * 256 + threadIdx.x;
    g_meta[i] = make_int2(resi[i], (chain[i] << 16) | batch[i]);
}

// ---------------------------------------------------------------------------
// Kernel 1: left/right projection GEMM
// ---------------------------------------------------------------------------
__global__ __launch_bounds__(256) void proj_kernel(
    const float* __restrict__ feat,
    const float* __restrict__ Wl,
    const float* __restrict__ Wr)
{
    __shared__ float As[32][68];
    __shared__ float Bs[32][64];

    const int t = threadIdx.x;
    const int tx = t & 15, ty = t >> 4;
    const int row0 = blockIdx.x * 64;

    float acc[4][4];
#pragma unroll
    for (int i = 0; i < 4; i++)
#pragma unroll
        for (int j = 0; j < 4; j++) acc[i][j] = 0.0f;

    const int lc = t & 31, lr = t >> 5, bcol = t & 63, bk0 = t >> 6;

    for (int cb = 0; cb < CDIM; cb += 32) {
#pragma unroll
        for (int it = 0; it < 8; it++)
            As[lc][lr + it * 8] = feat[(size_t)(row0 + lr + it * 8) * CDIM + cb + lc];
#pragma unroll
        for (int it = 0; it < 8; it++) {
            int kk = bk0 + it * 4;
            Bs[kk][bcol] = (bcol < PAIR) ? Wl[(cb + kk) * PAIR + bcol]
                                         : Wr[(cb + kk) * PAIR + (bcol - PAIR)];
        }
        __syncthreads();
#pragma unroll
        for (int kk = 0; kk < 32; kk++) {
            float4 a4 = *(const float4*)&As[kk][ty * 4];
            float4 b4 = *(const float4*)&Bs[kk][tx * 4];
            float av[4] = {a4.x, a4.y, a4.z, a4.w};
            float bv[4] = {b4.x, b4.y, b4.z, b4.w};
#pragma unroll
            for (int i = 0; i < 4; i++)
#pragma unroll
                for (int j = 0; j < 4; j++)
                    acc[i][j] = fmaf(av[i], bv[j], acc[i][j]);
        }
        __syncthreads();
    }

#pragma unroll
    for (int i = 0; i < 4; i++) {
        int row = row0 + ty * 4 + i;
#pragma unroll
        for (int j = 0; j < 4; j++) {
            int col = tx * 4 + j;
            if (col < PAIR) g_left[row * PAIR + col] = acc[i][j];
            else            g_right[row * PAIR + (col - PAIR)] = acc[i][j];
        }
    }
}

// ---------------------------------------------------------------------------
// Kernel 2: tiny tables: PP = Wpos@W1', S = colsum(W1'), B = lnb@W1 + b1
// ---------------------------------------------------------------------------
__global__ __launch_bounds__(64) void prep_kernel(
    const float* __restrict__ Wpos, const float* __restrict__ lns,
    const float* __restrict__ lnb,  const float* __restrict__ W1,
    const float* __restrict__ b1)
{
    __shared__ float tA[HID], tB[HID];
    const int j = threadIdx.x;

    if (blockIdx.x < NDR) {
        const int dr = blockIdx.x;
        float s = 0.0f;
#pragma unroll
        for (int i = 0; i < PAIR; i++)
            s = fmaf(Wpos[dr * PAIR + i] * lns[i], W1[i * HID + j], s);
        tA[j] = s;
        __syncthreads();
        if (j < HID / 2) PPg[dr * (HID / 2) + j] = pk2(tA[2 * j], tA[2 * j + 1]);
    } else {
        float s = 0.0f, b = 0.0f;
#pragma unroll
        for (int i = 0; i < PAIR; i++) {
            s = fmaf(lns[i], W1[i * HID + j], s);
            b = fmaf(lnb[i], W1[i * HID + j], b);
        }
        tA[j] = s; tB[j] = b + b1[j];
        __syncthreads();
        if (j < HID / 2) {
            Sg[j] = pk2(tA[2 * j], tA[2 * j + 1]);
            Bg[j] = pk2(tB[2 * j], tB[2 * j + 1]);
        }
    }
}

// ---------------------------------------------------------------------------
// Kernel 3: LP = g_left @ W1', RP = g_right @ W1'
// 8-way split per row: thread = (n, side, 8-slot group). grid NPTS/16.
// ---------------------------------------------------------------------------
__global__ __launch_bounds__(TPB) void lrproj_kernel(
    const float* __restrict__ lns, const float* __restrict__ W1)
{
    __shared__ __align__(16) u64 sW[PAIR][HID / 2];

    const int t = threadIdx.x;
    for (int idx = t; idx < PAIR * (HID / 2); idx += TPB) {
        int i = idx >> 5, s = idx & 31;
        float sc = lns[i];
        sW[i][s] = pk2(sc * W1[i * HID + 2 * s], sc * W1[i * HID + 2 * s + 1]);
    }
    __syncthreads();

    const int n    = blockIdx.x * 16 + (t >> 3);
    const int side = (t >> 2) & 1;
    const int s0   = (t & 3) * 8;              // slot group [s0, s0+8)

    const float* row = (side ? g_right : g_left) + (size_t)n * PAIR;
    u64 l2[PAIR];
    const float4* r4 = (const float4*)row;
#pragma unroll
    for (int q = 0; q < 8; q++) {
        float4 v = r4[q];                      // redundant x8 -> L1 broadcast hit
        l2[4 * q + 0] = pk2(v.x, v.x); l2[4 * q + 1] = pk2(v.y, v.y);
        l2[4 * q + 2] = pk2(v.z, v.z); l2[4 * q + 3] = pk2(v.w, v.w);
    }
    u64* dst = (side ? RPg : LPg) + (size_t)n * (HID / 2);
#pragma unroll
    for (int s = s0; s < s0 + 8; s++) {
        u64 acc = 0;
#pragma unroll
        for (int i = 0; i < PAIR; i++) acc = f2fma(l2[i], sW[i][s], acc);
        dst[s] = acc;
    }
}

// ---------------------------------------------------------------------------
// Kernel 4: per-pair pipeline via table recomposition (Round-12 form,
// 4 blocks/SM) + next-iteration neigh/meta prefetch to hide the L2 chain.
// ---------------------------------------------------------------------------
__global__ __launch_bounds__(TPB, 4) void pair_kernel(
    const int*   __restrict__ neigh,
    const float* __restrict__ Wpos,
    const float* __restrict__ W2,
    const float* __restrict__ b2,
    float* __restrict__ out_logp,
    float* __restrict__ out_dmap)
{
    __shared__ __align__(16) u64 sPP[NDR][HID / 2];        // 16.6 KB
    __shared__ __align__(16) u64 sWposp[NDR][PAIR / 2];    // 8.3 KB (stats path)
    __shared__ __align__(16) u64 sW2p[HID][BINS / 2];      // 4 KB, pre-halved
    __shared__ __align__(16) u64 sLP[NPB][HID / 2];        // 4 KB
    __shared__ __align__(16) u64 sleft[NPB][PAIR / 2];     // 2 KB
    __shared__ __align__(16) ulonglong2 sSB[HID / 2];      // (S, B) fused: 512 B
    __shared__ u64 sb2p[BINS / 2];
    __shared__ int sres[NPB], skey[NPB];

    const int t = threadIdx.x;
    const int bn = blockIdx.x * NPB;

    for (int idx = t; idx < NDR * (HID / 2); idx += TPB)
        ((u64*)sPP)[idx] = PPg[idx];
    for (int idx = t; idx < NDR * (PAIR / 2); idx += TPB) {
        int i2 = idx & 15, r = idx >> 4;
        sWposp[r][i2] = pk2(Wpos[r * PAIR + 2 * i2], Wpos[r * PAIR + 2 * i2 + 1]);
    }
    for (int idx = t; idx < HID * (BINS / 2); idx += TPB) {
        int b2i = idx & 7, j = idx >> 3;
        sW2p[j][b2i] = pk2(0.5f * W2[j * BINS + 2 * b2i],
                           0.5f * W2[j * BINS + 2 * b2i + 1]);
    }
    for (int idx = t; idx < NPB * (HID / 2); idx += TPB) {
        int nloc = idx >> 5, s = idx & 31;
        ((u64*)sLP)[idx] = LPg[(size_t)(bn + nloc) * (HID / 2) + s];
    }
    for (int idx = t; idx < NPB * (PAIR / 2); idx += TPB) {
        int nloc = idx >> 4, i2 = idx & 15;
        int n = bn + nloc;
        sleft[nloc][i2] = pk2(g_left[n * PAIR + 2 * i2], g_left[n * PAIR + 2 * i2 + 1]);
    }
    if (t < HID / 2) { sSB[t].x = Sg[t]; sSB[t].y = Bg[t]; }
    if (t < BINS / 2) sb2p[t] = pk2(b2[2 * t], b2[2 * t + 1]);
    if (t < NPB) { int2 m = g_meta[bn + t]; sres[t] = m.x; skey[t] = m.y; }
    __syncthreads();

    // prefetch iteration 0's neighbour ids + metadata
    int nbN[PMUX];
    int2 mtN[PMUX];
#pragma unroll
    for (int p = 0; p < PMUX; p++)
        nbN[p] = neigh[blockIdx.x * BPAIRS + t + p * TPB];
#pragma unroll
    for (int p = 0; p < PMUX; p++) mtN[p] = g_meta[nbN[p]];

#pragma unroll 1
    for (int o = 0; o < OUTER; o++) {
        const int lbase = o * (PMUX * TPB) + t;
        int pid[PMUX], nb[PMUX], nloc[PMUX], dr[PMUX];
        u64 sel2[PMUX], rs2[PMUX], cS[PMUX];
        int2 mt[PMUX];

#pragma unroll
        for (int p = 0; p < PMUX; p++) {
            pid[p]  = blockIdx.x * BPAIRS + lbase + p * TPB;
            nloc[p] = (lbase + p * TPB) >> 6;
            nb[p]   = nbN[p];
            mt[p]   = mtN[p];
        }
        // software pipeline: issue next iteration's neigh->meta chain now,
        // so its L2 latency overlaps this iteration's compute.
        if (o + 1 < OUTER) {
            const int lb2 = (o + 1) * (PMUX * TPB) + t;
#pragma unroll
            for (int p = 0; p < PMUX; p++)
                nbN[p] = neigh[blockIdx.x * BPAIRS + lb2 + p * TPB];
#pragma unroll
            for (int p = 0; p < PMUX; p++) mtN[p] = g_meta[nbN[p]];
        }

#pragma unroll
        for (int p = 0; p < PMUX; p++) {
            int d = mt[p].x - sres[nloc[p]];
            dr[p] = min(max(d, -CLIPV), CLIPV) + CLIPV;
            sel2[p] = (mt[p].y == skey[nloc[p]]) ? pk2(1.0f, 1.0f) : 0ULL;
        }

        // ---- streaming LN stats from raw right row ----
#pragma unroll
        for (int p = 0; p < PMUX; p++) {
            const ulonglong2* rr = (const ulonglong2*)(g_right + (size_t)nb[p] * PAIR);
            u64 s2 = 0, q2 = 0;
#pragma unroll
            for (int q = 0; q < 8; q++) {
                ulonglong2 v = rr[q];
                u64 e0 = f2add(v.x, sleft[nloc[p]][2 * q]);
                e0 = f2fma(sWposp[dr[p]][2 * q], sel2[p], e0);
                s2 = f2add(s2, e0); q2 = f2fma(e0, e0, q2);
                u64 e1 = f2add(v.y, sleft[nloc[p]][2 * q + 1]);
                e1 = f2fma(sWposp[dr[p]][2 * q + 1], sel2[p], e1);
                s2 = f2add(s2, e1); q2 = f2fma(e1, e1, q2);
            }
            float2 sf = upk2(s2), qf = upk2(q2);
            float mu  = (sf.x + sf.y) * (1.0f / PAIR);
            float var = (qf.x + qf.y) * (1.0f / PAIR) - mu * mu;
            float rs  = rsqrtf(var + LN_EPS);
            rs2[p] = pk2(rs, rs);
            cS[p]  = pk2(-rs * mu, -rs * mu);
        }

        // ---- hidden units via table recomposition + gelu + W2 ----
        u64 lg2[PMUX][BINS / 2];
#pragma unroll
        for (int p = 0; p < PMUX; p++)
#pragma unroll
            for (int b = 0; b < BINS / 2; b++) lg2[p][b] = sb2p[b];

        const ulonglong2* rpp[PMUX];
#pragma unroll
        for (int p = 0; p < PMUX; p++)
            rpp[p] = (const ulonglong2*)(RPg + (size_t)nb[p] * (HID / 2));

#pragma unroll 1
        for (int c = 0; c < 8; c++) {
            u64 rp4[PMUX][4];
#pragma unroll
            for (int p = 0; p < PMUX; p++) {
                ulonglong2 v0 = rpp[p][2 * c];
                ulonglong2 v1 = rpp[p][2 * c + 1];
                rp4[p][0] = v0.x; rp4[p][1] = v0.y;
                rp4[p][2] = v1.x; rp4[p][3] = v1.y;
            }
#pragma unroll
            for (int s4 = 0; s4 < 4; s4++) {
                const int gs = c * 4 + s4;
                const ulonglong2 sbv = sSB[gs];
                u64 h0[PMUX], h1[PMUX];
#pragma unroll
                for (int p = 0; p < PMUX; p++) {
                    u64 T = f2add(rp4[p][s4], sLP[nloc[p]][gs]);
                    T = f2fma(sPP[dr[p]][gs], sel2[p], T);
                    u64 a2 = f2fma(rs2[p], T, f2fma(cS[p], sbv.x, sbv.y));
                    float2 af = upk2(a2);
                    float aA = af.x, aB = af.y;
                    float uA = aA * fmaf(0.0356774081f, aA * aA, 0.7978845608f);
                    float uB = aB * fmaf(0.0356774081f, aB * aB, 0.7978845608f);
                    float tA = tanh_approx(uA);
                    float tB = tanh_approx(uB);
                    float hA = fmaf(aA, tA, aA);     // = 2*gelu, 0.5 in W2
                    float hB = fmaf(aB, tB, aB);
                    h0[p] = pk2(hA, hA); h1[p] = pk2(hB, hB);
                }
                const ulonglong2* wa = (const ulonglong2*)sW2p[2 * gs];
                const ulonglong2* wb = (const ulonglong2*)sW2p[2 * gs + 1];
#pragma unroll
                for (int q = 0; q < 4; q++) {
                    ulonglong2 va = wa[q];
                    ulonglong2 vb = wb[q];
#pragma unroll
                    for (int p = 0; p < PMUX; p++) {
                        lg2[p][2 * q]     = f2fma(h0[p], va.x, lg2[p][2 * q]);
                        lg2[p][2 * q + 1] = f2fma(h0[p], va.y, lg2[p][2 * q + 1]);
                        lg2[p][2 * q]     = f2fma(h1[p], vb.x, lg2[p][2 * q]);
                        lg2[p][2 * q + 1] = f2fma(h1[p], vb.y, lg2[p][2 * q + 1]);
                    }
                }
            }
        }

        // ---- log_softmax + expected distance + store ----
#pragma unroll
        for (int p = 0; p < PMUX; p++) {
            float l[BINS];
#pragma unroll
            for (int b = 0; b < BINS / 2; b++) {
                float2 f = upk2(lg2[p][b]);
                l[2 * b] = f.x; l[2 * b + 1] = f.y;
            }
            float m = l[0];
#pragma unroll
            for (int b = 1; b < BINS; b++) m = fmaxf(m, l[b]);
            const float mm = -m * LOG2E;
            float s = 0.0f, ws = 0.0f;
#pragma unroll
            for (int b = 0; b < BINS; b++) {
                float e = ex2f(fmaf(l[b], LOG2E, mm));
                s += e;
                ws = fmaf(e, ((float)b + 0.5f) * 1.375f, ws);
            }
            const float ofs = m + __logf(s);

            float* op = out_logp + (size_t)pid[p] * BINS;
#pragma unroll
            for (int b4 = 0; b4 < BINS / 4; b4++) {
                float4 ov;
                ov.x = l[b4 * 4 + 0] - ofs;
                ov.y = l[b4 * 4 + 1] - ofs;
                ov.z = l[b4 * 4 + 2] - ofs;
                ov.w = l[b4 * 4 + 3] - ofs;
                __stcs((float4*)(op + b4 * 4), ov);
            }
            __stcs(out_dmap + pid[p], __fdividef(ws, s));
        }
    }
}

// ---------------------------------------------------------------------------
extern "C" void kernel_launch(void* const* d_in, const int* in_sizes, int n_in,
                              void* d_out, int out_size)
{
    const float* feat  = (const float*)d_in[0];
    const int*   resi  = (const int*)  d_in[1];
    const int*   chain = (const int*)  d_in[2];
    const int*   batch = (const int*)  d_in[3];
    const int*   neigh = (const int*)  d_in[4];
    const float* Wl    = (const float*)d_in[5];
    const float* Wr    = (const float*)d_in[6];
    const float* Wpos  = (const float*)d_in[7];
    const float* lns   = (const float*)d_in[8];
    const float* lnb   = (const float*)d_in[9];
    const float* W1    = (const float*)d_in[10];
    const float* b1    = (const float*)d_in[11];
    const float* W2    = (const float*)d_in[12];
    const float* b2    = (const float*)d_in[13];

    float* out_logp = (float*)d_out;
    float* out_dmap = (float*)d_out + (size_t)NPAIRS * BINS;

    meta_kernel<<<NPTS / 256, 256>>>(resi, chain, batch);
    proj_kernel<<<NPTS / 64, 256>>>(feat, Wl, Wr);
    prep_kernel<<<NDR + 1, 64>>>(Wpos, lns, lnb, W1, b1);
    lrproj_kernel<<<NPTS / 16, TPB>>>(lns, W1);
    pair_kernel<<<NPAIRS / BPAIRS, TPB>>>(neigh, Wpos, W2, b2,
                                          out_logp, out_dmap);
}

// round 16
// speedup vs baseline: 1.6978x; 1.6978x over previous
#include <cuda_runtime.h>

#define NPTS 32768
#define KNB  64
#define CDIM 256
#define PAIR 32
#define HID  64
#define BINS 16
#define CLIPV 32
#define NDR  (2 * CLIPV + 1)
#define LN_EPS 1e-5f
#define PMUX 2            // pairs per thread per outer iter
#define OUTER 4           // outer iterations per block
#define TPB  128          // 1024 pairs/block, 16 n's/block
#define NPB  16
#define BPAIRS (TPB * PMUX * OUTER)
#define NPAIRS (NPTS * KNB)
#define LOG2E 1.4426950408889634f

typedef unsigned long long u64;

// Scratch (allocation-free rule -> __device__ globals)
static __device__ __align__(256) float g_left[NPTS * PAIR];     // 4 MB
static __device__ __align__(256) float g_right[NPTS * PAIR];    // 4 MB
static __device__ int2  g_meta[NPTS];
static __device__ __align__(256) u64 LPg[NPTS * (HID / 2)];     // 8 MB: left @ W1'
static __device__ __align__(256) u64 RPg[NPTS * (HID / 2)];     // 8 MB: right @ W1'
static __device__ __align__(16)  u64 PPg[NDR * (HID / 2)];      // Wpos @ W1'
static __device__ u64 Sg[HID / 2];                              // col sums of W1'
static __device__ u64 Bg[HID / 2];                              // lnb@W1 + b1

// ---------------- packed f32x2 helpers (FFMA2: PTX-only on sm_103a) --------
__device__ __forceinline__ u64 pk2(float lo, float hi) {
    u64 r; asm("mov.b64 %0,{%1,%2};" : "=l"(r) : "f"(lo), "f"(hi)); return r;
}
__device__ __forceinline__ float2 upk2(u64 v) {
    float2 f; asm("mov.b64 {%0,%1},%2;" : "=f"(f.x), "=f"(f.y) : "l"(v)); return f;
}
__device__ __forceinline__ u64 f2fma(u64 a, u64 b, u64 c) {
    u64 r; asm("fma.rn.f32x2 %0,%1,%2,%3;" : "=l"(r) : "l"(a), "l"(b), "l"(c)); return r;
}
__device__ __forceinline__ u64 f2add(u64 a, u64 b) {
    u64 r; asm("add.rn.f32x2 %0,%1,%2;" : "=l"(r) : "l"(a), "l"(b)); return r;
}
__device__ __forceinline__ float tanh_approx(float x) {
    float r; asm("tanh.approx.f32 %0,%1;" : "=f"(r) : "f"(x)); return r;
}
__device__ __forceinline__ float ex2f(float x) {
    float r; asm("ex2.approx.f32 %0,%1;" : "=f"(r) : "f"(x)); return r;
}

// ---------------------------------------------------------------------------
// Kernel 0: pack per-residue metadata
// ---------------------------------------------------------------------------
__global__ __launch_bounds__(256) void meta_kernel(
    const int* __restrict__ resi, const int* __restrict__ chain,
    const int* __restrict__ batch)
{
    int i = blockIdx.x * 256 + threadIdx.x;
    g_meta[i] = make_int2(resi[i], (chain[i] << 16) | batch[i]);
}

// ---------------------------------------------------------------------------
// Kernel 1: left/right projection GEMM
// ---------------------------------------------------------------------------
__global__ __launch_bounds__(256) void proj_kernel(
    const float* __restrict__ feat,
    const float* __restrict__ Wl,
    const float* __restrict__ Wr)
{
    __shared__ float As[32][68];
    __shared__ float Bs[32][64];

    const int t = threadIdx.x;
    const int tx = t & 15, ty = t >> 4;
    const int row0 = blockIdx.x * 64;

    float acc[4][4];
#pragma unroll
    for (int i = 0; i < 4; i++)
#pragma unroll
        for (int j = 0; j < 4; j++) acc[i][j] = 0.0f;

    const int lc = t & 31, lr = t >> 5, bcol = t & 63, bk0 = t >> 6;

    for (int cb = 0; cb < CDIM; cb += 32) {
#pragma unroll
        for (int it = 0; it < 8; it++)
            As[lc][lr + it * 8] = feat[(size_t)(row0 + lr + it * 8) * CDIM + cb + lc];
#pragma unroll
        for (int it = 0; it < 8; it++) {
            int kk = bk0 + it * 4;
            Bs[kk][bcol] = (bcol < PAIR) ? Wl[(cb + kk) * PAIR + bcol]
                                         : Wr[(cb + kk) * PAIR + (bcol - PAIR)];
        }
        __syncthreads();
#pragma unroll
        for (int kk = 0; kk < 32; kk++) {
            float4 a4 = *(const float4*)&As[kk][ty * 4];
            float4 b4 = *(const float4*)&Bs[kk][tx * 4];
            float av[4] = {a4.x, a4.y, a4.z, a4.w};
            float bv[4] = {b4.x, b4.y, b4.z, b4.w};
#pragma unroll
            for (int i = 0; i < 4; i++)
#pragma unroll
                for (int j = 0; j < 4; j++)
                    acc[i][j] = fmaf(av[i], bv[j], acc[i][j]);
        }
        __syncthreads();
    }

#pragma unroll
    for (int i = 0; i < 4; i++) {
        int row = row0 + ty * 4 + i;
#pragma unroll
        for (int j = 0; j < 4; j++) {
            int col = tx * 4 + j;
            if (col < PAIR) g_left[row * PAIR + col] = acc[i][j];
            else            g_right[row * PAIR + (col - PAIR)] = acc[i][j];
        }
    }
}

// ---------------------------------------------------------------------------
// Kernel 2: tiny tables: PP = Wpos@W1', S = colsum(W1'), B = lnb@W1 + b1
// ---------------------------------------------------------------------------
__global__ __launch_bounds__(64) void prep_kernel(
    const float* __restrict__ Wpos, const float* __restrict__ lns,
    const float* __restrict__ lnb,  const float* __restrict__ W1,
    const float* __restrict__ b1)
{
    __shared__ float tA[HID], tB[HID];
    const int j = threadIdx.x;

    if (blockIdx.x < NDR) {
        const int dr = blockIdx.x;
        float s = 0.0f;
#pragma unroll
        for (int i = 0; i < PAIR; i++)
            s = fmaf(Wpos[dr * PAIR + i] * lns[i], W1[i * HID + j], s);
        tA[j] = s;
        __syncthreads();
        if (j < HID / 2) PPg[dr * (HID / 2) + j] = pk2(tA[2 * j], tA[2 * j + 1]);
    } else {
        float s = 0.0f, b = 0.0f;
#pragma unroll
        for (int i = 0; i < PAIR; i++) {
            s = fmaf(lns[i], W1[i * HID + j], s);
            b = fmaf(lnb[i], W1[i * HID + j], b);
        }
        tA[j] = s; tB[j] = b + b1[j];
        __syncthreads();
        if (j < HID / 2) {
            Sg[j] = pk2(tA[2 * j], tA[2 * j + 1]);
            Bg[j] = pk2(tB[2 * j], tB[2 * j + 1]);
        }
    }
}

// ---------------------------------------------------------------------------
// Kernel 3: LP = g_left @ W1', RP = g_right @ W1'
// Split by (n, side): 1 thread = 1 row -> 1 table. No redundant loads.
// grid NPTS/64, 128 threads: t>>1 = n-within-block, t&1 = side.
// ---------------------------------------------------------------------------
__global__ __launch_bounds__(TPB) void lrproj_kernel(
    const float* __restrict__ lns, const float* __restrict__ W1)
{
    __shared__ __align__(16) u64 sW[PAIR][HID / 2];

    const int t = threadIdx.x;
    for (int idx = t; idx < PAIR * (HID / 2); idx += TPB) {
        int i = idx >> 5, s = idx & 31;
        float sc = lns[i];
        sW[i][s] = pk2(sc * W1[i * HID + 2 * s], sc * W1[i * HID + 2 * s + 1]);
    }
    __syncthreads();

    const int n    = blockIdx.x * 64 + (t >> 1);
    const int side = t & 1;

    const float* row = (side ? g_right : g_left) + (size_t)n * PAIR;
    u64 l2[PAIR];
    const float4* r4 = (const float4*)row;
#pragma unroll
    for (int q = 0; q < 8; q++) {
        float4 v = r4[q];
        l2[4 * q + 0] = pk2(v.x, v.x); l2[4 * q + 1] = pk2(v.y, v.y);
        l2[4 * q + 2] = pk2(v.z, v.z); l2[4 * q + 3] = pk2(v.w, v.w);
    }
    u64* dst = (side ? RPg : LPg) + (size_t)n * (HID / 2);
#pragma unroll 4
    for (int s = 0; s < HID / 2; s++) {
        u64 acc = 0;
#pragma unroll
        for (int i = 0; i < PAIR; i++) acc = f2fma(l2[i], sW[i][s], acc);
        dst[s] = acc;
    }
}

// ---------------------------------------------------------------------------
// Kernel 4: per-pair pipeline via table recomposition (Round-12 form,
// exactly: 4 blocks/SM, no prefetch, no pid array changes).
// ---------------------------------------------------------------------------
__global__ __launch_bounds__(TPB, 4) void pair_kernel(
    const int*   __restrict__ neigh,
    const float* __restrict__ Wpos,
    const float* __restrict__ W2,
    const float* __restrict__ b2,
    float* __restrict__ out_logp,
    float* __restrict__ out_dmap)
{
    __shared__ __align__(16) u64 sPP[NDR][HID / 2];        // 16.6 KB
    __shared__ __align__(16) u64 sWposp[NDR][PAIR / 2];    // 8.3 KB (stats path)
    __shared__ __align__(16) u64 sW2p[HID][BINS / 2];      // 4 KB, pre-halved
    __shared__ __align__(16) u64 sLP[NPB][HID / 2];        // 4 KB
    __shared__ __align__(16) u64 sleft[NPB][PAIR / 2];     // 2 KB
    __shared__ __align__(16) ulonglong2 sSB[HID / 2];      // (S, B) fused: 512 B
    __shared__ u64 sb2p[BINS / 2];
    __shared__ int sres[NPB], skey[NPB];

    const int t = threadIdx.x;
    const int bn = blockIdx.x * NPB;

    for (int idx = t; idx < NDR * (HID / 2); idx += TPB)
        ((u64*)sPP)[idx] = PPg[idx];
    for (int idx = t; idx < NDR * (PAIR / 2); idx += TPB) {
        int i2 = idx & 15, r = idx >> 4;
        sWposp[r][i2] = pk2(Wpos[r * PAIR + 2 * i2], Wpos[r * PAIR + 2 * i2 + 1]);
    }
    for (int idx = t; idx < HID * (BINS / 2); idx += TPB) {
        int b2i = idx & 7, j = idx >> 3;
        sW2p[j][b2i] = pk2(0.5f * W2[j * BINS + 2 * b2i],
                           0.5f * W2[j * BINS + 2 * b2i + 1]);
    }
    for (int idx = t; idx < NPB * (HID / 2); idx += TPB) {
        int nloc = idx >> 5, s = idx & 31;
        ((u64*)sLP)[idx] = LPg[(size_t)(bn + nloc) * (HID / 2) + s];
    }
    for (int idx = t; idx < NPB * (PAIR / 2); idx += TPB) {
        int nloc = idx >> 4, i2 = idx & 15;
        int n = bn + nloc;
        sleft[nloc][i2] = pk2(g_left[n * PAIR + 2 * i2], g_left[n * PAIR + 2 * i2 + 1]);
    }
    if (t < HID / 2) { sSB[t].x = Sg[t]; sSB[t].y = Bg[t]; }
    if (t < BINS / 2) sb2p[t] = pk2(b2[2 * t], b2[2 * t + 1]);
    if (t < NPB) { int2 m = g_meta[bn + t]; sres[t] = m.x; skey[t] = m.y; }
    __syncthreads();

#pragma unroll 1
    for (int o = 0; o < OUTER; o++) {
        const int lbase = o * (PMUX * TPB) + t;
        int pid[PMUX], nb[PMUX], nloc[PMUX], dr[PMUX];
        u64 sel2[PMUX], rs2[PMUX], cS[PMUX];

#pragma unroll
        for (int p = 0; p < PMUX; p++) {
            pid[p]  = blockIdx.x * BPAIRS + lbase + p * TPB;
            nloc[p] = (lbase + p * TPB) >> 6;
            nb[p]   = neigh[pid[p]];
        }
        int2 mt[PMUX];
#pragma unroll
        for (int p = 0; p < PMUX; p++) mt[p] = g_meta[nb[p]];
#pragma unroll
        for (int p = 0; p < PMUX; p++) {
            int d = mt[p].x - sres[nloc[p]];
            dr[p] = min(max(d, -CLIPV), CLIPV) + CLIPV;
            sel2[p] = (mt[p].y == skey[nloc[p]]) ? pk2(1.0f, 1.0f) : 0ULL;
        }

        // ---- streaming LN stats from raw right row ----
#pragma unroll
        for (int p = 0; p < PMUX; p++) {
            const ulonglong2* rr = (const ulonglong2*)(g_right + (size_t)nb[p] * PAIR);
            u64 s2 = 0, q2 = 0;
#pragma unroll
            for (int q = 0; q < 8; q++) {
                ulonglong2 v = rr[q];
                u64 e0 = f2add(v.x, sleft[nloc[p]][2 * q]);
                e0 = f2fma(sWposp[dr[p]][2 * q], sel2[p], e0);
                s2 = f2add(s2, e0); q2 = f2fma(e0, e0, q2);
                u64 e1 = f2add(v.y, sleft[nloc[p]][2 * q + 1]);
                e1 = f2fma(sWposp[dr[p]][2 * q + 1], sel2[p], e1);
                s2 = f2add(s2, e1); q2 = f2fma(e1, e1, q2);
            }
            float2 sf = upk2(s2), qf = upk2(q2);
            float mu  = (sf.x + sf.y) * (1.0f / PAIR);
            float var = (qf.x + qf.y) * (1.0f / PAIR) - mu * mu;
            float rs  = rsqrtf(var + LN_EPS);
            rs2[p] = pk2(rs, rs);
            cS[p]  = pk2(-rs * mu, -rs * mu);
        }

        // ---- hidden units via table recomposition + gelu + W2 ----
        u64 lg2[PMUX][BINS / 2];
#pragma unroll
        for (int p = 0; p < PMUX; p++)
#pragma unroll
            for (int b = 0; b < BINS / 2; b++) lg2[p][b] = sb2p[b];

        const ulonglong2* rpp[PMUX];
#pragma unroll
        for (int p = 0; p < PMUX; p++)
            rpp[p] = (const ulonglong2*)(RPg + (size_t)nb[p] * (HID / 2));

#pragma unroll 1
        for (int c = 0; c < 8; c++) {
            u64 rp4[PMUX][4];
#pragma unroll
            for (int p = 0; p < PMUX; p++) {
                ulonglong2 v0 = rpp[p][2 * c];
                ulonglong2 v1 = rpp[p][2 * c + 1];
                rp4[p][0] = v0.x; rp4[p][1] = v0.y;
                rp4[p][2] = v1.x; rp4[p][3] = v1.y;
            }
#pragma unroll
            for (int s4 = 0; s4 < 4; s4++) {
                const int gs = c * 4 + s4;
                const ulonglong2 sbv = sSB[gs];
                u64 h0[PMUX], h1[PMUX];
#pragma unroll
                for (int p = 0; p < PMUX; p++) {
                    u64 T = f2add(rp4[p][s4], sLP[nloc[p]][gs]);
                    T = f2fma(sPP[dr[p]][gs], sel2[p], T);
                    u64 a2 = f2fma(rs2[p], T, f2fma(cS[p], sbv.x, sbv.y));
                    float2 af = upk2(a2);
                    float aA = af.x, aB = af.y;
                    float uA = aA * fmaf(0.0356774081f, aA * aA, 0.7978845608f);
                    float uB = aB * fmaf(0.0356774081f, aB * aB, 0.7978845608f);
                    float tA = tanh_approx(uA);
                    float tB = tanh_approx(uB);
                    float hA = fmaf(aA, tA, aA);     // = 2*gelu, 0.5 in W2
                    float hB = fmaf(aB, tB, aB);
                    h0[p] = pk2(hA, hA); h1[p] = pk2(hB, hB);
                }
                const ulonglong2* wa = (const ulonglong2*)sW2p[2 * gs];
                const ulonglong2* wb = (const ulonglong2*)sW2p[2 * gs + 1];
#pragma unroll
                for (int q = 0; q < 4; q++) {
                    ulonglong2 va = wa[q];
                    ulonglong2 vb = wb[q];
#pragma unroll
                    for (int p = 0; p < PMUX; p++) {
                        lg2[p][2 * q]     = f2fma(h0[p], va.x, lg2[p][2 * q]);
                        lg2[p][2 * q + 1] = f2fma(h0[p], va.y, lg2[p][2 * q + 1]);
                        lg2[p][2 * q]     = f2fma(h1[p], vb.x, lg2[p][2 * q]);
                        lg2[p][2 * q + 1] = f2fma(h1[p], vb.y, lg2[p][2 * q + 1]);
                    }
                }
            }
        }

        // ---- log_softmax + expected distance + store ----
#pragma unroll
        for (int p = 0; p < PMUX; p++) {
            float l[BINS];
#pragma unroll
            for (int b = 0; b < BINS / 2; b++) {
                float2 f = upk2(lg2[p][b]);
                l[2 * b] = f.x; l[2 * b + 1] = f.y;
            }
            float m = l[0];
#pragma unroll
            for (int b = 1; b < BINS; b++) m = fmaxf(m, l[b]);
            const float mm = -m * LOG2E;
            float s = 0.0f, ws = 0.0f;
#pragma unroll
            for (int b = 0; b < BINS; b++) {
                float e = ex2f(fmaf(l[b], LOG2E, mm));
                s += e;
                ws = fmaf(e, ((float)b + 0.5f) * 1.375f, ws);
            }
            const float ofs = m + __logf(s);

            float* op = out_logp + (size_t)pid[p] * BINS;
#pragma unroll
            for (int b4 = 0; b4 < BINS / 4; b4++) {
                float4 ov;
                ov.x = l[b4 * 4 + 0] - ofs;
                ov.y = l[b4 * 4 + 1] - ofs;
                ov.z = l[b4 * 4 + 2] - ofs;
                ov.w = l[b4 * 4 + 3] - ofs;
                __stcs((float4*)(op + b4 * 4), ov);
            }
            __stcs(out_dmap + pid[p], __fdividef(ws, s));
        }
    }
}

// ---------------------------------------------------------------------------
extern "C" void kernel_launch(void* const* d_in, const int* in_sizes, int n_in,
                              void* d_out, int out_size)
{
    const float* feat  = (const float*)d_in[0];
    const int*   resi  = (const int*)  d_in[1];
    const int*   chain = (const int*)  d_in[2];
    const int*   batch = (const int*)  d_in[3];
    const int*   neigh = (const int*)  d_in[4];
    const float* Wl    = (const float*)d_in[5];
    const float* Wr    = (const float*)d_in[6];
    const float* Wpos  = (const float*)d_in[7];
    const float* lns   = (const float*)d_in[8];
    const float* lnb   = (const float*)d_in[9];
    const float* W1    = (const float*)d_in[10];
    const float* b1    = (const float*)d_in[11];
    const float* W2    = (const float*)d_in[12];
    const float* b2    = (const float*)d_in[13];

    float* out_logp = (float*)d_out;
    float* out_dmap = (float*)d_out + (size_t)NPAIRS * BINS;

    meta_kernel<<<NPTS / 256, 256>>>(resi, chain, batch);
    proj_kernel<<<NPTS / 64, 256>>>(feat, Wl, Wr);
    prep_kernel<<<NDR + 1, 64>>>(Wpos, lns, lnb, W1, b1);
    lrproj_kernel<<<NPTS / 64, TPB>>>(lns, W1);
    pair_kernel<<<NPAIRS / BPAIRS, TPB>>>(neigh, Wpos, W2, b2,
                                          out_logp, out_dmap);
}